// round 1
// baseline (speedup 1.0000x reference)
#include <cuda_runtime.h>
#include <cuda_bf16.h>
#include <math.h>

// Problem constants
#define HH 96
#define WW 96
#define BB 4
#define CIN 64
#define HW (HH*WW)

// ---------------- scratch (no allocations allowed) ----------------
__device__ float g_om[(size_t)BB * 216 * HW];   // offset-conv output (oy|ox|mask-logits)
__device__ float g_fea[(size_t)BB * 64 * HW];   // leakyrelu(dcn) output

// =================================================================
// Kernel A: direct 3x3 conv, pad 1, Cin=64.
// Tile: TH=32 x TW=16 pixels, 256 threads, each thread 2 pixels x COB channels.
// Weights staged in smem transposed to [ci*9+tap][COB] for LDS.128.
// =================================================================
constexpr int CIB = 8;
constexpr int TH  = 32;
constexpr int TW  = 16;

template<int COB, bool RESID>
__global__ __launch_bounds__(256) void conv3x3_k(
    const float* __restrict__ in, const float* __restrict__ w,
    const float* __restrict__ bias, const float* __restrict__ resid,
    float* __restrict__ out, int Cout)
{
    __shared__ float s_in[CIB * (TH + 2) * (TW + 2)];
    __shared__ __align__(16) float s_w[CIB * 9 * COB];

    const int tid = threadIdx.x;
    const int tx = tid & 15;
    const int ty = tid >> 4;           // 0..15
    const int tb = blockIdx.x;         // 0..17
    const int hy0 = (tb / 6) * TH;
    const int wx0 = (tb % 6) * TW;
    const int co0 = blockIdx.y * COB;
    const int b   = blockIdx.z;

    const float* inb = in + (size_t)b * CIN * HW;

    float acc0[COB], acc1[COB];
#pragma unroll
    for (int o = 0; o < COB; o++) { acc0[o] = 0.f; acc1[o] = 0.f; }

    for (int ci0 = 0; ci0 < CIN; ci0 += CIB) {
        __syncthreads();
        // stage input tile (with halo, zero-padded)
        for (int e = tid; e < CIB * (TH + 2) * (TW + 2); e += 256) {
            int ci = e / ((TH + 2) * (TW + 2));
            int r  = e - ci * ((TH + 2) * (TW + 2));
            int yy = r / (TW + 2);
            int xx = r - yy * (TW + 2);
            int gy = hy0 + yy - 1;
            int gx = wx0 + xx - 1;
            float v = 0.f;
            if ((unsigned)gy < HH && (unsigned)gx < WW)
                v = inb[(ci0 + ci) * HW + gy * WW + gx];
            s_in[e] = v;
        }
        // stage weights transposed: s_w[(ci*9+tap)*COB + o]
        for (int e = tid; e < CIB * 9 * COB; e += 256) {
            int rest = e / COB;            // ci*9 + tap (local)
            int o    = e - rest * COB;
            s_w[e] = w[(size_t)(co0 + o) * (CIN * 9) + ci0 * 9 + rest];
        }
        __syncthreads();

#pragma unroll 1
        for (int ci = 0; ci < CIB; ci++) {
#pragma unroll
            for (int ky = 0; ky < 3; ky++) {
#pragma unroll
                for (int kx = 0; kx < 3; kx++) {
                    float a0 = s_in[ci * (TH + 2) * (TW + 2) + (ty + ky) * (TW + 2) + tx + kx];
                    float a1 = s_in[ci * (TH + 2) * (TW + 2) + (ty + 16 + ky) * (TW + 2) + tx + kx];
                    const float4* wr = (const float4*)&s_w[(ci * 9 + ky * 3 + kx) * COB];
#pragma unroll
                    for (int j = 0; j < COB / 4; j++) {
                        float4 wv = wr[j];
                        acc0[4*j+0] = fmaf(a0, wv.x, acc0[4*j+0]);
                        acc1[4*j+0] = fmaf(a1, wv.x, acc1[4*j+0]);
                        acc0[4*j+1] = fmaf(a0, wv.y, acc0[4*j+1]);
                        acc1[4*j+1] = fmaf(a1, wv.y, acc1[4*j+1]);
                        acc0[4*j+2] = fmaf(a0, wv.z, acc0[4*j+2]);
                        acc1[4*j+2] = fmaf(a1, wv.z, acc1[4*j+2]);
                        acc0[4*j+3] = fmaf(a0, wv.w, acc0[4*j+3]);
                        acc1[4*j+3] = fmaf(a1, wv.w, acc1[4*j+3]);
                    }
                }
            }
        }
    }

    const int py0 = hy0 + ty;
    const int px  = wx0 + tx;
#pragma unroll
    for (int o = 0; o < COB; o++) {
        float bb = bias[co0 + o];
        size_t i0 = ((size_t)(b * Cout + co0 + o) * HH + py0) * WW + px;
        size_t i1 = i0 + (size_t)16 * WW;
        float r0 = acc0[o] + bb;
        float r1 = acc1[o] + bb;
        if (RESID) { r0 += resid[i0]; r1 += resid[i1]; }
        out[i0] = r0;
        out[i1] = r1;
    }
}

// =================================================================
// Kernel B: deformable sampling + grouped einsum + LeakyReLU.
// One thread = one (b,h,w) pixel, 64 fp32 accumulators.
// w_dcn transposed in dynamic smem as wds[g][k][o][c] (144 KB).
// =================================================================
__global__ __launch_bounds__(256) void deform_dcn_k(
    const float* __restrict__ x, const float* __restrict__ om,
    const float* __restrict__ wdcn, const float* __restrict__ bdcn,
    float* __restrict__ fea)
{
    extern __shared__ __align__(16) float wds[];  // [72][64][8] = 36864 floats

    const int tid = threadIdx.x;
    // transpose w_dcn [o][g*8+c][k] -> wds[(g*9+k)*512 + o*8 + c]
    for (int e = tid; e < 64 * 576; e += 256) {
        int c  = e & 7;
        int o  = (e >> 3) & 63;
        int gk = e >> 9;              // 0..71
        int g  = gk / 9;
        int k  = gk - g * 9;
        wds[e] = wdcn[(size_t)(o * 64 + g * 8 + c) * 9 + k];
    }
    __syncthreads();

    const int tx  = tid & 31;
    const int tyl = tid >> 5;
    const int w0 = blockIdx.x * 32 + tx;
    const int h0 = blockIdx.y * 8 + tyl;
    const int b  = blockIdx.z;

    const float* omb = om + (size_t)b * 216 * HW;
    const float* xb  = x  + (size_t)b * 64  * HW;
    const int pidx = h0 * WW + w0;

    float acc[64];
#pragma unroll
    for (int o = 0; o < 64; o++) acc[o] = 0.f;

#pragma unroll 1
    for (int g = 0; g < 8; g++) {
        const float* xg = xb + g * 8 * HW;
#pragma unroll 1
        for (int k = 0; k < 9; k++) {
            const int gk = g * 9 + k;
            float oy = omb[(size_t)gk * HW + pidx];
            float ox = omb[(size_t)(72 + gk) * HW + pidx];
            float ml = omb[(size_t)(144 + gk) * HW + pidx];
            float m  = 1.f / (1.f + __expf(-ml));

            float py = (float)(h0 + (k / 3) - 1) + oy;
            float px = (float)(w0 + (k % 3) - 1) + ox;
            float y0f = floorf(py), x0f = floorf(px);
            float fy = py - y0f, fx = px - x0f;
            int y0 = (int)y0f, x0 = (int)x0f;
            int y1 = y0 + 1,  x1 = x0 + 1;

            float vy0 = (y0 >= 0 && y0 < HH) ? 1.f : 0.f;
            float vy1 = (y1 >= 0 && y1 < HH) ? 1.f : 0.f;
            float vx0 = (x0 >= 0 && x0 < WW) ? 1.f : 0.f;
            float vx1 = (x1 >= 0 && x1 < WW) ? 1.f : 0.f;
            int yc0 = min(max(y0, 0), HH - 1);
            int yc1 = min(max(y1, 0), HH - 1);
            int xc0 = min(max(x0, 0), WW - 1);
            int xc1 = min(max(x1, 0), WW - 1);

            float w00 = (1.f - fy) * (1.f - fx) * vy0 * vx0 * m;
            float w01 = (1.f - fy) * fx        * vy0 * vx1 * m;
            float w10 = fy        * (1.f - fx) * vy1 * vx0 * m;
            float w11 = fy        * fx         * vy1 * vx1 * m;

            int i00 = yc0 * WW + xc0;
            int i01 = yc0 * WW + xc1;
            int i10 = yc1 * WW + xc0;
            int i11 = yc1 * WW + xc1;

            float v[8];
#pragma unroll
            for (int c = 0; c < 8; c++) {
                const float* xc = xg + c * HW;
                v[c] = w00 * __ldg(xc + i00) + w01 * __ldg(xc + i01)
                     + w10 * __ldg(xc + i10) + w11 * __ldg(xc + i11);
            }

            const float4* wp = (const float4*)(wds + (size_t)gk * 512);
#pragma unroll
            for (int o = 0; o < 64; o++) {
                float4 a  = wp[o * 2];
                float4 bq = wp[o * 2 + 1];
                float s = v[0] * a.x;
                s = fmaf(v[1], a.y, s);
                s = fmaf(v[2], a.z, s);
                s = fmaf(v[3], a.w, s);
                s = fmaf(v[4], bq.x, s);
                s = fmaf(v[5], bq.y, s);
                s = fmaf(v[6], bq.z, s);
                s = fmaf(v[7], bq.w, s);
                acc[o] += s;
            }
        }
    }

#pragma unroll
    for (int o = 0; o < 64; o++) {
        float d = acc[o] + bdcn[o];
        fea[(size_t)(b * 64 + o) * HW + pidx] = (d >= 0.f) ? d : 0.2f * d;
    }
}

// =================================================================
// Launch
// =================================================================
extern "C" void kernel_launch(void* const* d_in, const int* in_sizes, int n_in,
                              void* d_out, int out_size)
{
    const float* x       = (const float*)d_in[0];
    const float* offset  = (const float*)d_in[1];
    const float* w_off   = (const float*)d_in[2];
    const float* b_off   = (const float*)d_in[3];
    const float* w_dcn   = (const float*)d_in[4];
    const float* b_dcn   = (const float*)d_in[5];
    const float* w_conv1 = (const float*)d_in[6];
    const float* b_conv1 = (const float*)d_in[7];
    float* out = (float*)d_out;

    void* p_om = nullptr;
    void* p_fea = nullptr;
    cudaGetSymbolAddress(&p_om, g_om);
    cudaGetSymbolAddress(&p_fea, g_fea);
    float* om  = (float*)p_om;
    float* fea = (float*)p_fea;

    cudaFuncSetAttribute(deform_dcn_k, cudaFuncAttributeMaxDynamicSharedMemorySize,
                         64 * 576 * (int)sizeof(float));

    // 1) offset conv: 64 -> 216 channels
    conv3x3_k<24, false><<<dim3(18, 9, BB), 256>>>(offset, w_off, b_off, nullptr, om, 216);

    // 2) deformable sampling + grouped einsum + leakyrelu
    deform_dcn_k<<<dim3(3, 12, BB), 256, 64 * 576 * sizeof(float)>>>(x, om, w_dcn, b_dcn, fea);

    // 3) conv1: 64 -> 64 channels, + bias + residual x
    conv3x3_k<16, true><<<dim3(18, 4, BB), 256>>>(fea, w_conv1, b_conv1, x, out, 64);
}

// round 2
// speedup vs baseline: 1.0165x; 1.0165x over previous
#include <cuda_runtime.h>
#include <cuda_bf16.h>
#include <math.h>

// Problem constants
#define HH 96
#define WW 96
#define BB 4
#define CIN 64
#define HW (HH*WW)

// ---------------- scratch (no allocations allowed) ----------------
__device__ float g_om[(size_t)BB * 216 * HW];   // offset-conv output (oy|ox|mask-logits)
__device__ float g_fea[(size_t)BB * 64 * HW];   // leakyrelu(dcn) output

// ---------------- packed f32x2 helpers (Blackwell FFMA2) ----------------
__device__ __forceinline__ unsigned long long pk2(float lo, float hi) {
    unsigned long long r;
    asm("mov.b64 %0, {%1, %2};" : "=l"(r) : "f"(lo), "f"(hi));
    return r;
}
__device__ __forceinline__ unsigned long long fma2(unsigned long long a,
                                                   unsigned long long b,
                                                   unsigned long long c) {
    unsigned long long d;
    asm("fma.rn.f32x2 %0, %1, %2, %3;" : "=l"(d) : "l"(a), "l"(b), "l"(c));
    return d;
}
__device__ __forceinline__ void upk2(unsigned long long v, float& lo, float& hi) {
    asm("mov.b64 {%0, %1}, %2;" : "=f"(lo), "=f"(hi) : "l"(v));
}

// =================================================================
// Kernel A: direct 3x3 conv, pad 1, Cin=64, packed-f32x2 inner loop.
// Tile: TH=32 x TW=16 pixels, 256 threads, each thread 2 pixels x COB channels.
// Weights staged in smem transposed to [ci*9+tap][COB]; LDS.128 yields two
// adjacent output-channel pairs, consumed directly by fma.rn.f32x2.
// =================================================================
constexpr int CIB = 8;
constexpr int TH  = 32;
constexpr int TW  = 16;

template<int COB, bool RESID>
__global__ __launch_bounds__(256) void conv3x3_k(
    const float* __restrict__ in, const float* __restrict__ w,
    const float* __restrict__ bias, const float* __restrict__ resid,
    float* __restrict__ out, int Cout)
{
    __shared__ float s_in[CIB * (TH + 2) * (TW + 2)];
    __shared__ __align__(16) float s_w[CIB * 9 * COB];

    const int tid = threadIdx.x;
    const int tx = tid & 15;
    const int ty = tid >> 4;           // 0..15
    const int tb = blockIdx.x;         // 0..17
    const int hy0 = (tb / 6) * TH;
    const int wx0 = (tb % 6) * TW;
    const int co0 = blockIdx.y * COB;
    const int b   = blockIdx.z;

    const float* inb = in + (size_t)b * CIN * HW;

    unsigned long long accp0[COB / 2], accp1[COB / 2];
#pragma unroll
    for (int j = 0; j < COB / 2; j++) { accp0[j] = 0ull; accp1[j] = 0ull; }

    for (int ci0 = 0; ci0 < CIN; ci0 += CIB) {
        __syncthreads();
        // stage input tile (with halo, zero-padded)
        for (int e = tid; e < CIB * (TH + 2) * (TW + 2); e += 256) {
            int ci = e / ((TH + 2) * (TW + 2));
            int r  = e - ci * ((TH + 2) * (TW + 2));
            int yy = r / (TW + 2);
            int xx = r - yy * (TW + 2);
            int gy = hy0 + yy - 1;
            int gx = wx0 + xx - 1;
            float v = 0.f;
            if ((unsigned)gy < HH && (unsigned)gx < WW)
                v = inb[(ci0 + ci) * HW + gy * WW + gx];
            s_in[e] = v;
        }
        // stage weights transposed: s_w[(ci*9+tap)*COB + o]
        for (int e = tid; e < CIB * 9 * COB; e += 256) {
            int rest = e / COB;            // ci*9 + tap (local)
            int o    = e - rest * COB;
            s_w[e] = w[(size_t)(co0 + o) * (CIN * 9) + ci0 * 9 + rest];
        }
        __syncthreads();

#pragma unroll 1
        for (int ci = 0; ci < CIB; ci++) {
#pragma unroll
            for (int ky = 0; ky < 3; ky++) {
#pragma unroll
                for (int kx = 0; kx < 3; kx++) {
                    float a0 = s_in[ci * (TH + 2) * (TW + 2) + (ty + ky) * (TW + 2) + tx + kx];
                    float a1 = s_in[ci * (TH + 2) * (TW + 2) + (ty + 16 + ky) * (TW + 2) + tx + kx];
                    unsigned long long a0p = pk2(a0, a0);
                    unsigned long long a1p = pk2(a1, a1);
                    const ulonglong2* wr = (const ulonglong2*)&s_w[(ci * 9 + ky * 3 + kx) * COB];
#pragma unroll
                    for (int j = 0; j < COB / 4; j++) {
                        ulonglong2 wv = wr[j];        // pairs (w[4j],w[4j+1]) , (w[4j+2],w[4j+3])
                        accp0[2*j]   = fma2(a0p, wv.x, accp0[2*j]);
                        accp1[2*j]   = fma2(a1p, wv.x, accp1[2*j]);
                        accp0[2*j+1] = fma2(a0p, wv.y, accp0[2*j+1]);
                        accp1[2*j+1] = fma2(a1p, wv.y, accp1[2*j+1]);
                    }
                }
            }
        }
    }

    const int py0 = hy0 + ty;
    const int px  = wx0 + tx;
#pragma unroll
    for (int j = 0; j < COB / 2; j++) {
        float a0lo, a0hi, a1lo, a1hi;
        upk2(accp0[j], a0lo, a0hi);
        upk2(accp1[j], a1lo, a1hi);
        int o_lo = 2 * j, o_hi = 2 * j + 1;
        float blo = bias[co0 + o_lo];
        float bhi = bias[co0 + o_hi];
        size_t i0lo = ((size_t)(b * Cout + co0 + o_lo) * HH + py0) * WW + px;
        size_t i0hi = ((size_t)(b * Cout + co0 + o_hi) * HH + py0) * WW + px;
        size_t i1lo = i0lo + (size_t)16 * WW;
        size_t i1hi = i0hi + (size_t)16 * WW;
        float r0lo = a0lo + blo, r0hi = a0hi + bhi;
        float r1lo = a1lo + blo, r1hi = a1hi + bhi;
        if (RESID) {
            r0lo += resid[i0lo]; r0hi += resid[i0hi];
            r1lo += resid[i1lo]; r1hi += resid[i1hi];
        }
        out[i0lo] = r0lo; out[i0hi] = r0hi;
        out[i1lo] = r1lo; out[i1hi] = r1hi;
    }
}

// =================================================================
// Kernel B: deformable sampling + grouped einsum + LeakyReLU.
// One thread = one (b,h,w) pixel, 32 packed fp32x2 accumulators (64 ch).
// w_dcn transposed in dynamic smem as wds[gk][c][o] (o contiguous for
// packed pairs): 72*8*64 floats = 144 KB.
// =================================================================
__global__ __launch_bounds__(256) void deform_dcn_k(
    const float* __restrict__ x, const float* __restrict__ om,
    const float* __restrict__ wdcn, const float* __restrict__ bdcn,
    float* __restrict__ fea)
{
    extern __shared__ __align__(16) float wds[];  // [72][8][64] = 36864 floats

    const int tid = threadIdx.x;
    // transpose w_dcn [o][g*8+c][k] -> wds[((g*9+k)*8 + c)*64 + o]
    for (int e = tid; e < 64 * 576; e += 256) {
        int o  = e & 63;
        int c  = (e >> 6) & 7;
        int gk = e >> 9;              // 0..71
        int g  = gk / 9;
        int k  = gk - g * 9;
        wds[e] = wdcn[(size_t)(o * 64 + g * 8 + c) * 9 + k];
    }
    __syncthreads();

    const int tx  = tid & 31;
    const int tyl = tid >> 5;
    const int w0 = blockIdx.x * 32 + tx;
    const int h0 = blockIdx.y * 8 + tyl;
    const int b  = blockIdx.z;

    const float* omb = om + (size_t)b * 216 * HW;
    const float* xb  = x  + (size_t)b * 64  * HW;
    const int pidx = h0 * WW + w0;

    unsigned long long accp[32];
#pragma unroll
    for (int j = 0; j < 32; j++) accp[j] = 0ull;

#pragma unroll 1
    for (int g = 0; g < 8; g++) {
        const float* xg = xb + g * 8 * HW;
#pragma unroll 1
        for (int k = 0; k < 9; k++) {
            const int gk = g * 9 + k;
            float oy = omb[(size_t)gk * HW + pidx];
            float ox = omb[(size_t)(72 + gk) * HW + pidx];
            float ml = omb[(size_t)(144 + gk) * HW + pidx];
            float m  = 1.f / (1.f + __expf(-ml));

            float py = (float)(h0 + (k / 3) - 1) + oy;
            float px = (float)(w0 + (k % 3) - 1) + ox;
            float y0f = floorf(py), x0f = floorf(px);
            float fy = py - y0f, fx = px - x0f;
            int y0 = (int)y0f, x0 = (int)x0f;
            int y1 = y0 + 1,  x1 = x0 + 1;

            float vy0 = (y0 >= 0 && y0 < HH) ? 1.f : 0.f;
            float vy1 = (y1 >= 0 && y1 < HH) ? 1.f : 0.f;
            float vx0 = (x0 >= 0 && x0 < WW) ? 1.f : 0.f;
            float vx1 = (x1 >= 0 && x1 < WW) ? 1.f : 0.f;
            int yc0 = min(max(y0, 0), HH - 1);
            int yc1 = min(max(y1, 0), HH - 1);
            int xc0 = min(max(x0, 0), WW - 1);
            int xc1 = min(max(x1, 0), WW - 1);

            float w00 = (1.f - fy) * (1.f - fx) * vy0 * vx0 * m;
            float w01 = (1.f - fy) * fx        * vy0 * vx1 * m;
            float w10 = fy        * (1.f - fx) * vy1 * vx0 * m;
            float w11 = fy        * fx         * vy1 * vx1 * m;

            int i00 = yc0 * WW + xc0;
            int i01 = yc0 * WW + xc1;
            int i10 = yc1 * WW + xc0;
            int i11 = yc1 * WW + xc1;

            float v[8];
#pragma unroll
            for (int c = 0; c < 8; c++) {
                const float* xc = xg + c * HW;
                v[c] = w00 * __ldg(xc + i00) + w01 * __ldg(xc + i01)
                     + w10 * __ldg(xc + i10) + w11 * __ldg(xc + i11);
            }

#pragma unroll
            for (int c = 0; c < 8; c++) {
                unsigned long long vp = pk2(v[c], v[c]);
                const ulonglong2* wp = (const ulonglong2*)(wds + ((size_t)gk * 8 + c) * 64);
#pragma unroll
                for (int j = 0; j < 16; j++) {
                    ulonglong2 wv = wp[j];   // (w[4j],w[4j+1]) , (w[4j+2],w[4j+3])
                    accp[2*j]   = fma2(vp, wv.x, accp[2*j]);
                    accp[2*j+1] = fma2(vp, wv.y, accp[2*j+1]);
                }
            }
        }
    }

#pragma unroll
    for (int j = 0; j < 32; j++) {
        float lo, hi;
        upk2(accp[j], lo, hi);
        int o_lo = 2 * j, o_hi = 2 * j + 1;
        float dlo = lo + bdcn[o_lo];
        float dhi = hi + bdcn[o_hi];
        fea[(size_t)(b * 64 + o_lo) * HW + pidx] = (dlo >= 0.f) ? dlo : 0.2f * dlo;
        fea[(size_t)(b * 64 + o_hi) * HW + pidx] = (dhi >= 0.f) ? dhi : 0.2f * dhi;
    }
}

// =================================================================
// Launch
// =================================================================
extern "C" void kernel_launch(void* const* d_in, const int* in_sizes, int n_in,
                              void* d_out, int out_size)
{
    const float* x       = (const float*)d_in[0];
    const float* offset  = (const float*)d_in[1];
    const float* w_off   = (const float*)d_in[2];
    const float* b_off   = (const float*)d_in[3];
    const float* w_dcn   = (const float*)d_in[4];
    const float* b_dcn   = (const float*)d_in[5];
    const float* w_conv1 = (const float*)d_in[6];
    const float* b_conv1 = (const float*)d_in[7];
    float* out = (float*)d_out;

    void* p_om = nullptr;
    void* p_fea = nullptr;
    cudaGetSymbolAddress(&p_om, g_om);
    cudaGetSymbolAddress(&p_fea, g_fea);
    float* om  = (float*)p_om;
    float* fea = (float*)p_fea;

    cudaFuncSetAttribute(deform_dcn_k, cudaFuncAttributeMaxDynamicSharedMemorySize,
                         64 * 576 * (int)sizeof(float));

    // 1) offset conv: 64 -> 216 channels
    conv3x3_k<24, false><<<dim3(18, 9, BB), 256>>>(offset, w_off, b_off, nullptr, om, 216);

    // 2) deformable sampling + grouped einsum + leakyrelu
    deform_dcn_k<<<dim3(3, 12, BB), 256, 64 * 576 * sizeof(float)>>>(x, om, w_dcn, b_dcn, fea);

    // 3) conv1: 64 -> 64 channels, + bias + residual x
    conv3x3_k<16, true><<<dim3(18, 4, BB), 256>>>(fea, w_conv1, b_conv1, x, out, 64);
}

// round 4
// speedup vs baseline: 1.0235x; 1.0069x over previous
#include <cuda_runtime.h>
#include <cuda_bf16.h>
#include <math.h>

// Problem constants
#define HH 96
#define WW 96
#define BB 4
#define CIN 64
#define HW (HH*WW)

// ---------------- scratch (no allocations allowed) ----------------
__device__ float g_om[(size_t)BB * 216 * HW];        // offset-conv output
__device__ float g_fea[(size_t)2 * BB * 64 * HW];    // raw partial dcn sums (g-halves)

// ---------------- packed f32x2 helpers (Blackwell FFMA2) ----------------
__device__ __forceinline__ unsigned long long pk2(float lo, float hi) {
    unsigned long long r;
    asm("mov.b64 %0, {%1, %2};" : "=l"(r) : "f"(lo), "f"(hi));
    return r;
}
__device__ __forceinline__ unsigned long long fma2(unsigned long long a,
                                                   unsigned long long b,
                                                   unsigned long long c) {
    unsigned long long d;
    asm("fma.rn.f32x2 %0, %1, %2, %3;" : "=l"(d) : "l"(a), "l"(b), "l"(c));
    return d;
}
__device__ __forceinline__ void upk2(unsigned long long v, float& lo, float& hi) {
    asm("mov.b64 {%0, %1}, %2;" : "=f"(lo), "=f"(hi) : "l"(v));
}

// =================================================================
// Kernel A: direct 3x3 conv, pad 1, Cin=64, register-tiled.
// Tile: TH=48 x TW=16 pixels, 256 threads (16x16), each thread 3
// CONTIGUOUS rows x COB channels. Per ci: 5x3 input window in regs
// (15 LDS), per tap COB/4 weight LDS.128 feed 3*COB/2 FFMA2.
// PRE: fuse partial-sum + bias + LeakyReLU while staging input.
// =================================================================
constexpr int CIB = 8;
constexpr int TH  = 48;
constexpr int TW  = 16;
constexpr int SROW = TW + 2;             // 18
constexpr int SPLANE = (TH + 2) * SROW;  // 50*18 = 900

template<int COB, bool RESID, bool PRE>
__global__ __launch_bounds__(256, 2) void conv3x3_k(
    const float* __restrict__ in, const float* __restrict__ in2,
    const float* __restrict__ w,
    const float* __restrict__ bias, const float* __restrict__ pbias,
    const float* __restrict__ resid,
    float* __restrict__ out, int Cout)
{
    __shared__ float s_in[CIB * SPLANE];
    __shared__ __align__(16) float s_w[CIB * 9 * COB];

    const int tid = threadIdx.x;
    const int tx = tid & 15;
    const int ty = tid >> 4;           // 0..15
    const int tb = blockIdx.x;         // 0..11
    const int hy0 = (tb / 6) * TH;
    const int wx0 = (tb % 6) * TW;
    const int co0 = blockIdx.y * COB;
    const int b   = blockIdx.z;

    const float* inb  = in  + (size_t)b * CIN * HW;
    const float* in2b = PRE ? (in2 + (size_t)b * CIN * HW) : nullptr;

    unsigned long long acc[3][COB / 2];
#pragma unroll
    for (int p = 0; p < 3; p++)
#pragma unroll
        for (int j = 0; j < COB / 2; j++) acc[p][j] = 0ull;

    for (int ci0 = 0; ci0 < CIN; ci0 += CIB) {
        __syncthreads();
        // stage input tile (halo, zero-padded; PRE fuses sum+bias+leaky)
        for (int e = tid; e < CIB * SPLANE; e += 256) {
            int ci = e / SPLANE;
            int r  = e - ci * SPLANE;
            int yy = r / SROW;
            int xx = r - yy * SROW;
            int gy = hy0 + yy - 1;
            int gx = wx0 + xx - 1;
            float v = 0.f;
            if ((unsigned)gy < HH && (unsigned)gx < WW) {
                int gi = (ci0 + ci) * HW + gy * WW + gx;
                v = inb[gi];
                if (PRE) {
                    v += in2b[gi] + pbias[ci0 + ci];
                    v = (v >= 0.f) ? v : 0.2f * v;
                }
            }
            s_in[e] = v;
        }
        // stage weights transposed: s_w[(ci*9+tap)*COB + o]
        for (int e = tid; e < CIB * 9 * COB; e += 256) {
            int rest = e / COB;            // ci*9 + tap (local)
            int o    = e - rest * COB;
            s_w[e] = w[(size_t)(co0 + o) * (CIN * 9) + ci0 * 9 + rest];
        }
        __syncthreads();

#pragma unroll 1
        for (int ci = 0; ci < CIB; ci++) {
            // 5x3 register window: rows 3*ty..3*ty+4, cols tx..tx+2
            float rwin[5][3];
            const float* sp = &s_in[ci * SPLANE + (3 * ty) * SROW + tx];
#pragma unroll
            for (int rr = 0; rr < 5; rr++)
#pragma unroll
                for (int cc = 0; cc < 3; cc++)
                    rwin[rr][cc] = sp[rr * SROW + cc];

#pragma unroll
            for (int ky = 0; ky < 3; ky++) {
#pragma unroll
                for (int kx = 0; kx < 3; kx++) {
                    const ulonglong2* wr =
                        (const ulonglong2*)&s_w[(ci * 9 + ky * 3 + kx) * COB];
                    ulonglong2 wv[COB / 4];
#pragma unroll
                    for (int j = 0; j < COB / 4; j++) wv[j] = wr[j];
#pragma unroll
                    for (int p = 0; p < 3; p++) {
                        float a = rwin[p + ky][kx];
                        unsigned long long ap = pk2(a, a);
#pragma unroll
                        for (int j = 0; j < COB / 4; j++) {
                            acc[p][2*j]   = fma2(ap, wv[j].x, acc[p][2*j]);
                            acc[p][2*j+1] = fma2(ap, wv[j].y, acc[p][2*j+1]);
                        }
                    }
                }
            }
        }
    }

    const int px = wx0 + tx;
#pragma unroll
    for (int p = 0; p < 3; p++) {
        int py = hy0 + 3 * ty + p;
#pragma unroll
        for (int j = 0; j < COB / 2; j++) {
            float lo, hi;
            upk2(acc[p][j], lo, hi);
            int o_lo = 2 * j, o_hi = 2 * j + 1;
            float rlo = lo + bias[co0 + o_lo];
            float rhi = hi + bias[co0 + o_hi];
            size_t ilo = ((size_t)(b * Cout + co0 + o_lo) * HH + py) * WW + px;
            size_t ihi = ((size_t)(b * Cout + co0 + o_hi) * HH + py) * WW + px;
            if (RESID) { rlo += resid[ilo]; rhi += resid[ihi]; }
            out[ilo] = rlo;
            out[ihi] = rhi;
        }
    }
}

// =================================================================
// Kernel B: deformable sampling + grouped einsum (HALF the groups).
// One thread = one (b,h,w) pixel, 32 packed fp32x2 accumulators (64 ch),
// g in [gh*4, gh*4+4). Writes RAW partial sums (no bias/activation).
// Weights for 4 groups staged in 73.7 KB dynamic smem as [gkl][c][o].
// =================================================================
__global__ __launch_bounds__(256, 2) void deform_dcn_k(
    const float* __restrict__ x, const float* __restrict__ om,
    const float* __restrict__ wdcn,
    float* __restrict__ fea_part)   // [2][B][64][HW]
{
    extern __shared__ __align__(16) float wds[];  // [36][8][64] = 18432 floats

    const int tid = threadIdx.x;
    const int gh  = blockIdx.y & 1;        // group half
    const int hyt = blockIdx.y >> 1;       // 0..11
    const int b   = blockIdx.z;

    // transpose w_dcn [o][g*8+c][k] -> wds[((gl*9+k)*8 + c)*64 + o]
    for (int e = tid; e < 64 * 288; e += 256) {
        int o   = e & 63;
        int c   = (e >> 6) & 7;
        int gkl = e >> 9;              // 0..35
        int gl  = gkl / 9;
        int k   = gkl - gl * 9;
        int g   = gh * 4 + gl;
        wds[e] = wdcn[(size_t)(o * 64 + g * 8 + c) * 9 + k];
    }
    __syncthreads();

    const int tx  = tid & 31;
    const int tyl = tid >> 5;
    const int w0 = blockIdx.x * 32 + tx;
    const int h0 = hyt * 8 + tyl;

    const float* omb = om + (size_t)b * 216 * HW;
    const float* xb  = x  + (size_t)b * 64  * HW;
    const int pidx = h0 * WW + w0;

    unsigned long long accp[32];
#pragma unroll
    for (int j = 0; j < 32; j++) accp[j] = 0ull;

#pragma unroll 1
    for (int gl = 0; gl < 4; gl++) {
        const int g = gh * 4 + gl;
        const float* xg = xb + g * 8 * HW;
#pragma unroll 1
        for (int k = 0; k < 9; k++) {
            const int gk  = g * 9 + k;      // global (for offsets)
            const int gkl = gl * 9 + k;     // local (for weights)
            float oy = omb[(size_t)gk * HW + pidx];
            float ox = omb[(size_t)(72 + gk) * HW + pidx];
            float ml = omb[(size_t)(144 + gk) * HW + pidx];
            float m  = 1.f / (1.f + __expf(-ml));

            float py = (float)(h0 + (k / 3) - 1) + oy;
            float px = (float)(w0 + (k % 3) - 1) + ox;
            float y0f = floorf(py), x0f = floorf(px);
            float fy = py - y0f, fx = px - x0f;
            int y0 = (int)y0f, x0 = (int)x0f;
            int y1 = y0 + 1,  x1 = x0 + 1;

            float vy0 = (y0 >= 0 && y0 < HH) ? 1.f : 0.f;
            float vy1 = (y1 >= 0 && y1 < HH) ? 1.f : 0.f;
            float vx0 = (x0 >= 0 && x0 < WW) ? 1.f : 0.f;
            float vx1 = (x1 >= 0 && x1 < WW) ? 1.f : 0.f;
            int yc0 = min(max(y0, 0), HH - 1);
            int yc1 = min(max(y1, 0), HH - 1);
            int xc0 = min(max(x0, 0), WW - 1);
            int xc1 = min(max(x1, 0), WW - 1);

            float w00 = (1.f - fy) * (1.f - fx) * vy0 * vx0 * m;
            float w01 = (1.f - fy) * fx        * vy0 * vx1 * m;
            float w10 = fy        * (1.f - fx) * vy1 * vx0 * m;
            float w11 = fy        * fx         * vy1 * vx1 * m;

            int i00 = yc0 * WW + xc0;
            int i01 = yc0 * WW + xc1;
            int i10 = yc1 * WW + xc0;
            int i11 = yc1 * WW + xc1;

            float v[8];
#pragma unroll
            for (int c = 0; c < 8; c++) {
                const float* xc = xg + c * HW;
                v[c] = w00 * __ldg(xc + i00) + w01 * __ldg(xc + i01)
                     + w10 * __ldg(xc + i10) + w11 * __ldg(xc + i11);
            }

#pragma unroll
            for (int c = 0; c < 8; c++) {
                unsigned long long vp = pk2(v[c], v[c]);
                const ulonglong2* wp = (const ulonglong2*)(wds + ((size_t)gkl * 8 + c) * 64);
#pragma unroll
                for (int j = 0; j < 16; j++) {
                    ulonglong2 wv = wp[j];
                    accp[2*j]   = fma2(vp, wv.x, accp[2*j]);
                    accp[2*j+1] = fma2(vp, wv.y, accp[2*j+1]);
                }
            }
        }
    }

    float* fo = fea_part + ((size_t)gh * BB + b) * 64 * HW;
#pragma unroll
    for (int j = 0; j < 32; j++) {
        float lo, hi;
        upk2(accp[j], lo, hi);
        fo[(size_t)(2 * j) * HW + pidx]     = lo;
        fo[(size_t)(2 * j + 1) * HW + pidx] = hi;
    }
}

// =================================================================
// Launch
// =================================================================
extern "C" void kernel_launch(void* const* d_in, const int* in_sizes, int n_in,
                              void* d_out, int out_size)
{
    const float* x       = (const float*)d_in[0];
    const float* offset  = (const float*)d_in[1];
    const float* w_off   = (const float*)d_in[2];
    const float* b_off   = (const float*)d_in[3];
    const float* w_dcn   = (const float*)d_in[4];
    const float* b_dcn   = (const float*)d_in[5];
    const float* w_conv1 = (const float*)d_in[6];
    const float* b_conv1 = (const float*)d_in[7];
    float* out = (float*)d_out;

    void* p_om = nullptr;
    void* p_fea = nullptr;
    cudaGetSymbolAddress(&p_om, g_om);
    cudaGetSymbolAddress(&p_fea, g_fea);
    float* om  = (float*)p_om;
    float* fea = (float*)p_fea;

    const int DSMEM = 64 * 288 * (int)sizeof(float);   // 73728
    cudaFuncSetAttribute(deform_dcn_k, cudaFuncAttributeMaxDynamicSharedMemorySize, DSMEM);

    // 1) offset conv: 64 -> 216 channels  (COB=12, grid.y=18)
    conv3x3_k<12, false, false><<<dim3(12, 18, BB), 256>>>(
        offset, nullptr, w_off, b_off, nullptr, nullptr, om, 216);

    // 2) deformable sampling + grouped einsum, split over 2 group-halves
    deform_dcn_k<<<dim3(3, 24, BB), 256, DSMEM>>>(x, om, w_dcn, fea);

    // 3) conv1: 64 -> 64, staging fuses (fea0+fea1+b_dcn -> leaky), + residual x
    conv3x3_k<16, true, true><<<dim3(12, 4, BB), 256>>>(
        fea, fea + (size_t)BB * 64 * HW, w_conv1, b_conv1, b_dcn, x, out, 64);
}

// round 7
// speedup vs baseline: 1.8825x; 1.8393x over previous
#include <cuda_runtime.h>
#include <cuda_bf16.h>
#include <cstdint>
#include <math.h>

// Problem constants
#define HH 96
#define WW 96
#define BB 4
#define CIN 64
#define HW (HH*WW)

// ---------------- scratch (no allocations allowed) ----------------
__device__ float g_om[(size_t)BB * 216 * HW];        // offset-conv output
__device__ float g_fea[(size_t)2 * BB * 64 * HW];    // raw partial dcn sums (g-halves)
__device__ __nv_bfloat16 g_wAh[9 * 216 * 72];        // offset-conv weights hi [tap][o][72]
__device__ __nv_bfloat16 g_wAl[9 * 216 * 72];        // lo
__device__ __nv_bfloat16 g_wBh[9 * 64 * 72];         // conv1 weights hi
__device__ __nv_bfloat16 g_wBl[9 * 64 * 72];         // lo

// ---------------- packed f32x2 helpers (deform kernel) ----------------
__device__ __forceinline__ unsigned long long pk2(float lo, float hi) {
    unsigned long long r;
    asm("mov.b64 %0, {%1, %2};" : "=l"(r) : "f"(lo), "f"(hi));
    return r;
}
__device__ __forceinline__ unsigned long long fma2(unsigned long long a,
                                                   unsigned long long b,
                                                   unsigned long long c) {
    unsigned long long d;
    asm("fma.rn.f32x2 %0, %1, %2, %3;" : "=l"(d) : "l"(a), "l"(b), "l"(c));
    return d;
}
__device__ __forceinline__ void upk2(unsigned long long v, float& lo, float& hi) {
    asm("mov.b64 {%0, %1}, %2;" : "=f"(lo), "=f"(hi) : "l"(v));
}

// ---------------- warp MMA: m16n8k16 row.col f32.bf16.bf16.f32 ----------------
__device__ __forceinline__ void mma16816(float* d, const uint32_t* a, const uint32_t* b) {
    asm volatile(
        "mma.sync.aligned.m16n8k16.row.col.f32.bf16.bf16.f32 "
        "{%0,%1,%2,%3}, {%4,%5,%6,%7}, {%8,%9}, {%0,%1,%2,%3};"
        : "+f"(d[0]), "+f"(d[1]), "+f"(d[2]), "+f"(d[3])
        : "r"(a[0]), "r"(a[1]), "r"(a[2]), "r"(a[3]), "r"(b[0]), "r"(b[1]));
}

// =================================================================
// Weight prep: fp32 [Cout][64][3][3] -> bf16 hi/lo [tap][o][72-padded ci]
// =================================================================
__global__ void prep_w_k(const float* __restrict__ w,
                         __nv_bfloat16* __restrict__ oh,
                         __nv_bfloat16* __restrict__ ol, int Cout)
{
    int i = blockIdx.x * 256 + threadIdx.x;
    int total = 9 * Cout * 64;
    if (i >= total) return;
    int ci  = i & 63;
    int o   = (i >> 6) % Cout;
    int tap = i / (64 * Cout);
    float v = w[(size_t)(o * 64 + ci) * 9 + tap];
    __nv_bfloat16 h = __float2bfloat16(v);
    __nv_bfloat16 l = __float2bfloat16(v - __bfloat162float(h));
    size_t d = (size_t)(tap * Cout + o) * 72 + ci;
    oh[d] = h;
    ol[d] = l;
}

// =================================================================
// 3x3 conv (pad 1, Cin=64) via warp mma.sync bf16 hi/lo split.
// Block: 128 threads (4 warps). M=128 pixels (8 rows x 16 cols):
// warp w -> rows 2w, 2w+1 (two m16 tiles). N = NT*8 channels.
// K = 9 taps x 4 k16 chunks. Patch [pixel(10x18)][72ci] bf16 hi/lo in smem;
// weights [NT*8][72ci] per tap copied to smem.
// PRE: fuse (in + in2 + pbias -> leaky) at patch staging (conv1 path).
// RESID: add residual at epilogue.
// =================================================================
constexpr int PS = 72;                    // ci stride (elems) in patch & B tiles
constexpr int PATCH_E = 180 * PS;         // 10*18 pixels
constexpr int PATCH_BYTES = PATCH_E * 2;  // 25920

template<int NT, int NCHUNK, bool PRE, bool RESID>
__global__ __launch_bounds__(128) void conv_mma(
    const float* __restrict__ in, const float* __restrict__ in2,
    const float* __restrict__ pbias,
    const __nv_bfloat16* __restrict__ wh, const __nv_bfloat16* __restrict__ wl,
    const float* __restrict__ bias, const float* __restrict__ resid,
    float* __restrict__ out, int Cout)
{
    extern __shared__ __align__(16) char smem[];
    __nv_bfloat16* phi = (__nv_bfloat16*)smem;
    __nv_bfloat16* plo = (__nv_bfloat16*)(smem + PATCH_BYTES);
    __nv_bfloat16* bhiS = (__nv_bfloat16*)(smem + 2 * PATCH_BYTES);
    __nv_bfloat16* bloS = bhiS + NT * 8 * PS;

    const int tid  = threadIdx.x;
    const int wp   = tid >> 5;            // warp 0..3
    const int lane = tid & 31;
    const int qr   = lane >> 2;           // 0..7
    const int qc   = lane & 3;            // 0..3

    const int wx0 = blockIdx.x * 16;
    const int hy0 = blockIdx.y * 8;
    const int zz  = blockIdx.z;
    const int nc  = zz % NCHUNK;
    const int b   = zz / NCHUNK;
    const int co0 = nc * NT * 8;

    // ---- stage patch [10][18][64->72] bf16 hi/lo (zero halo; PRE fuses act) ----
    const float* inb  = in  + (size_t)b * CIN * HW;
    const float* in2b = PRE ? (in2 + (size_t)b * CIN * HW) : nullptr;
    for (int e = tid; e < 180 * 64; e += 128) {
        int x  = e % 18;
        int y  = (e / 18) % 10;
        int ci = e / 180;
        int gy = hy0 + y - 1;
        int gx = wx0 + x - 1;
        float v = 0.f;
        if ((unsigned)gy < HH && (unsigned)gx < WW) {
            int gi = ci * HW + gy * WW + gx;
            v = inb[gi];
            if (PRE) {
                v += in2b[gi] + pbias[ci];
                v = (v >= 0.f) ? v : 0.2f * v;
            }
        }
        __nv_bfloat16 h = __float2bfloat16(v);
        __nv_bfloat16 l = __float2bfloat16(v - __bfloat162float(h));
        int d = (y * 18 + x) * PS + ci;
        phi[d] = h;
        plo[d] = l;
    }

    float acc[2][NT][4];
#pragma unroll
    for (int mt = 0; mt < 2; mt++)
#pragma unroll
        for (int nt = 0; nt < NT; nt++)
#pragma unroll
            for (int j = 0; j < 4; j++) acc[mt][nt][j] = 0.f;

#pragma unroll 1
    for (int tap = 0; tap < 9; tap++) {
        const int ky = tap / 3, kx = tap % 3;
        __syncthreads();
        // copy this tap's weight tile (hi/lo) to smem, vectorized
        {
            const uint4* sH = (const uint4*)(wh + (size_t)(tap * Cout + co0) * PS);
            const uint4* sL = (const uint4*)(wl + (size_t)(tap * Cout + co0) * PS);
            uint4* dH = (uint4*)bhiS;
            uint4* dL = (uint4*)bloS;
            const int n4 = NT * 8 * PS / 8;   // uint4 count
            for (int e = tid; e < n4; e += 128) { dH[e] = sH[e]; dL[e] = sL[e]; }
        }
        __syncthreads();

#pragma unroll
        for (int kc = 0; kc < 4; kc++) {
            const int ci0 = kc * 16;
            uint32_t ah[2][4], al[2][4];
#pragma unroll
            for (int mt = 0; mt < 2; mt++) {
                int yrow = 2 * wp + mt + ky;                 // patch row
                int base = (yrow * 18 + qr + kx) * PS + ci0 + qc * 2;
                const uint32_t* ph = (const uint32_t*)phi;
                const uint32_t* pl = (const uint32_t*)plo;
                // elems/2 -> b32 index
                int i0 = base >> 1;
                int i1 = (base + 8 * PS) >> 1;
                ah[mt][0] = ph[i0];
                ah[mt][1] = ph[i1];
                ah[mt][2] = ph[i0 + 4];
                ah[mt][3] = ph[i1 + 4];
                al[mt][0] = pl[i0];
                al[mt][1] = pl[i1];
                al[mt][2] = pl[i0 + 4];
                al[mt][3] = pl[i1 + 4];
            }
#pragma unroll
            for (int nt = 0; nt < NT; nt++) {
                int bb = ((nt * 8 + qr) * PS + ci0 + qc * 2) >> 1;
                uint32_t bh[2], bl[2];
                bh[0] = ((const uint32_t*)bhiS)[bb];
                bh[1] = ((const uint32_t*)bhiS)[bb + 4];
                bl[0] = ((const uint32_t*)bloS)[bb];
                bl[1] = ((const uint32_t*)bloS)[bb + 4];
#pragma unroll
                for (int mt = 0; mt < 2; mt++) {
                    mma16816(acc[mt][nt], ah[mt], bh);
                    mma16816(acc[mt][nt], ah[mt], bl);
                    mma16816(acc[mt][nt], al[mt], bh);
                }
            }
        }
    }

    // ---- epilogue ----
#pragma unroll
    for (int mt = 0; mt < 2; mt++) {
        int gy = hy0 + 2 * wp + mt;
        int gx = wx0 + qr;
#pragma unroll
        for (int nt = 0; nt < NT; nt++) {
            int o = co0 + nt * 8 + qc * 2;
            float b0 = bias[o], b1 = bias[o + 1];
            size_t i00 = ((size_t)(b * Cout + o) * HH + gy) * WW + gx;
            size_t i01 = i00 + HW;       // channel o+1
            float v0 = acc[mt][nt][0] + b0;
            float v1 = acc[mt][nt][1] + b1;
            float v2 = acc[mt][nt][2] + b0;   // x+8
            float v3 = acc[mt][nt][3] + b1;
            if (RESID) {
                v0 += resid[i00];     v1 += resid[i01];
                v2 += resid[i00 + 8]; v3 += resid[i01 + 8];
            }
            out[i00] = v0;
            out[i01] = v1;
            out[i00 + 8] = v2;
            out[i01 + 8] = v3;
        }
    }
}

// =================================================================
// Kernel B: deformable sampling + grouped einsum (HALF the groups).
// One thread = one (b,h,w) pixel, 32 packed fp32x2 accumulators (64 ch),
// g in [gh*4, gh*4+4). Writes RAW partial sums (no bias/activation).
// =================================================================
__global__ __launch_bounds__(256, 2) void deform_dcn_k(
    const float* __restrict__ x, const float* __restrict__ om,
    const float* __restrict__ wdcn,
    float* __restrict__ fea_part)   // [2][B][64][HW]
{
    extern __shared__ __align__(16) float wds[];  // [36][8][64] = 18432 floats

    const int tid = threadIdx.x;
    const int gh  = blockIdx.y & 1;        // group half
    const int hyt = blockIdx.y >> 1;       // 0..11
    const int b   = blockIdx.z;

    for (int e = tid; e < 64 * 288; e += 256) {
        int o   = e & 63;
        int c   = (e >> 6) & 7;
        int gkl = e >> 9;              // 0..35
        int gl  = gkl / 9;
        int k   = gkl - gl * 9;
        int g   = gh * 4 + gl;
        wds[e] = wdcn[(size_t)(o * 64 + g * 8 + c) * 9 + k];
    }
    __syncthreads();

    const int tx  = tid & 31;
    const int tyl = tid >> 5;
    const int w0 = blockIdx.x * 32 + tx;
    const int h0 = hyt * 8 + tyl;

    const float* omb = om + (size_t)b * 216 * HW;
    const float* xb  = x  + (size_t)b * 64  * HW;
    const int pidx = h0 * WW + w0;

    unsigned long long accp[32];
#pragma unroll
    for (int j = 0; j < 32; j++) accp[j] = 0ull;

#pragma unroll 1
    for (int gl = 0; gl < 4; gl++) {
        const int g = gh * 4 + gl;
        const float* xg = xb + g * 8 * HW;
#pragma unroll 1
        for (int k = 0; k < 9; k++) {
            const int gk  = g * 9 + k;
            const int gkl = gl * 9 + k;
            float oy = omb[(size_t)gk * HW + pidx];
            float ox = omb[(size_t)(72 + gk) * HW + pidx];
            float ml = omb[(size_t)(144 + gk) * HW + pidx];
            float m  = 1.f / (1.f + __expf(-ml));

            float py = (float)(h0 + (k / 3) - 1) + oy;
            float px = (float)(w0 + (k % 3) - 1) + ox;
            float y0f = floorf(py), x0f = floorf(px);
            float fy = py - y0f, fx = px - x0f;
            int y0 = (int)y0f, x0 = (int)x0f;
            int y1 = y0 + 1,  x1 = x0 + 1;

            float vy0 = (y0 >= 0 && y0 < HH) ? 1.f : 0.f;
            float vy1 = (y1 >= 0 && y1 < HH) ? 1.f : 0.f;
            float vx0 = (x0 >= 0 && x0 < WW) ? 1.f : 0.f;
            float vx1 = (x1 >= 0 && x1 < WW) ? 1.f : 0.f;
            int yc0 = min(max(y0, 0), HH - 1);
            int yc1 = min(max(y1, 0), HH - 1);
            int xc0 = min(max(x0, 0), WW - 1);
            int xc1 = min(max(x1, 0), WW - 1);

            float w00 = (1.f - fy) * (1.f - fx) * vy0 * vx0 * m;
            float w01 = (1.f - fy) * fx        * vy0 * vx1 * m;
            float w10 = fy        * (1.f - fx) * vy1 * vx0 * m;
            float w11 = fy        * fx         * vy1 * vx1 * m;

            int i00 = yc0 * WW + xc0;
            int i01 = yc0 * WW + xc1;
            int i10 = yc1 * WW + xc0;
            int i11 = yc1 * WW + xc1;

            float v[8];
#pragma unroll
            for (int c = 0; c < 8; c++) {
                const float* xc = xg + c * HW;
                v[c] = w00 * __ldg(xc + i00) + w01 * __ldg(xc + i01)
                     + w10 * __ldg(xc + i10) + w11 * __ldg(xc + i11);
            }

#pragma unroll
            for (int c = 0; c < 8; c++) {
                unsigned long long vp = pk2(v[c], v[c]);
                const ulonglong2* wp = (const ulonglong2*)(wds + ((size_t)gkl * 8 + c) * 64);
#pragma unroll
                for (int j = 0; j < 16; j++) {
                    ulonglong2 wv = wp[j];
                    accp[2*j]   = fma2(vp, wv.x, accp[2*j]);
                    accp[2*j+1] = fma2(vp, wv.y, accp[2*j+1]);
                }
            }
        }
    }

    float* fo = fea_part + ((size_t)gh * BB + b) * 64 * HW;
#pragma unroll
    for (int j = 0; j < 32; j++) {
        float lo, hi;
        upk2(accp[j], lo, hi);
        fo[(size_t)(2 * j) * HW + pidx]     = lo;
        fo[(size_t)(2 * j + 1) * HW + pidx] = hi;
    }
}

// =================================================================
// Launch
// =================================================================
extern "C" void kernel_launch(void* const* d_in, const int* in_sizes, int n_in,
                              void* d_out, int out_size)
{
    const float* x       = (const float*)d_in[0];
    const float* offset  = (const float*)d_in[1];
    const float* w_off   = (const float*)d_in[2];
    const float* b_off   = (const float*)d_in[3];
    const float* w_dcn   = (const float*)d_in[4];
    const float* b_dcn   = (const float*)d_in[5];
    const float* w_conv1 = (const float*)d_in[6];
    const float* b_conv1 = (const float*)d_in[7];
    float* out = (float*)d_out;

    void *p_om, *p_fea, *p_wAh, *p_wAl, *p_wBh, *p_wBl;
    cudaGetSymbolAddress(&p_om, g_om);
    cudaGetSymbolAddress(&p_fea, g_fea);
    cudaGetSymbolAddress(&p_wAh, g_wAh);
    cudaGetSymbolAddress(&p_wAl, g_wAl);
    cudaGetSymbolAddress(&p_wBh, g_wBh);
    cudaGetSymbolAddress(&p_wBl, g_wBl);
    float* om  = (float*)p_om;
    float* fea = (float*)p_fea;

    const int SMEM_A = 2 * PATCH_BYTES + 2 * 9 * 8 * PS * 2;   // 51840 + 20736 = 72576
    const int SMEM_B = 2 * PATCH_BYTES + 2 * 8 * 8 * PS * 2;   // 51840 + 18432 = 70272
    const int DSMEM  = 64 * 288 * (int)sizeof(float);          // 73728

    cudaFuncSetAttribute((const void*)conv_mma<9, 3, false, false>,
                         cudaFuncAttributeMaxDynamicSharedMemorySize, SMEM_A);
    cudaFuncSetAttribute((const void*)conv_mma<8, 1, true, true>,
                         cudaFuncAttributeMaxDynamicSharedMemorySize, SMEM_B);
    cudaFuncSetAttribute((const void*)deform_dcn_k,
                         cudaFuncAttributeMaxDynamicSharedMemorySize, DSMEM);

    // 0) weight prep (hi/lo split, [tap][o][72] layout)
    prep_w_k<<<(9 * 216 * 64 + 255) / 256, 256>>>(w_off,  (__nv_bfloat16*)p_wAh, (__nv_bfloat16*)p_wAl, 216);
    prep_w_k<<<(9 * 64 * 64 + 255) / 256, 256>>>(w_conv1, (__nv_bfloat16*)p_wBh, (__nv_bfloat16*)p_wBl, 64);

    // 1) offset conv: 64 -> 216 (mma.sync), 3 chunks of 72 channels
    conv_mma<9, 3, false, false><<<dim3(6, 12, BB * 3), 128, SMEM_A>>>(
        offset, nullptr, nullptr,
        (const __nv_bfloat16*)p_wAh, (const __nv_bfloat16*)p_wAl,
        b_off, nullptr, om, 216);

    // 2) deformable sampling + grouped einsum, split over 2 group-halves
    deform_dcn_k<<<dim3(3, 24, BB), 256, DSMEM>>>(x, om, w_dcn, fea);

    // 3) conv1: 64 -> 64 (mma.sync), staging fuses (fea0+fea1+b_dcn -> leaky), + residual
    conv_mma<8, 1, true, true><<<dim3(6, 12, BB), 128, SMEM_B>>>(
        fea, fea + (size_t)BB * 64 * HW, b_dcn,
        (const __nv_bfloat16*)p_wBh, (const __nv_bfloat16*)p_wBl,
        b_conv1, x, out, 64);
}

// round 8
// speedup vs baseline: 2.3617x; 1.2546x over previous
#include <cuda_runtime.h>
#include <cuda_bf16.h>
#include <cstdint>
#include <math.h>

// Problem constants
#define HH 96
#define WW 96
#define BB 4
#define CIN 64
#define HW (HH*WW)

// ---------------- scratch (no allocations allowed) ----------------
__device__ float g_om[(size_t)BB * 216 * HW];        // offset-conv output
__device__ float g_fea[(size_t)BB * 64 * HW];        // activated dcn output
__device__ __nv_bfloat16 g_wAh[9 * 216 * 72];        // offset-conv weights hi [tap][o][72]
__device__ __nv_bfloat16 g_wAl[9 * 216 * 72];        // lo
__device__ __nv_bfloat16 g_wBh[9 * 64 * 72];         // conv1 weights hi
__device__ __nv_bfloat16 g_wBl[9 * 64 * 72];         // lo
__device__ uint2 g_fragH[36 * 8 * 32];               // w_dcn bf16-hi fragments [chunk][nt][lane]
__device__ uint2 g_fragL[36 * 8 * 32];               // lo fragments

// ---------------- warp MMA: m16n8k16 row.col f32.bf16.bf16.f32 ----------------
__device__ __forceinline__ void mma16816(float* d, const uint32_t* a, const uint32_t* b) {
    asm volatile(
        "mma.sync.aligned.m16n8k16.row.col.f32.bf16.bf16.f32 "
        "{%0,%1,%2,%3}, {%4,%5,%6,%7}, {%8,%9}, {%0,%1,%2,%3};"
        : "+f"(d[0]), "+f"(d[1]), "+f"(d[2]), "+f"(d[3])
        : "r"(a[0]), "r"(a[1]), "r"(a[2]), "r"(a[3]), "r"(b[0]), "r"(b[1]));
}

__device__ __forceinline__ uint32_t pack_bf16x2(float a, float b) {
    __nv_bfloat16 ha = __float2bfloat16(a);
    __nv_bfloat16 hb = __float2bfloat16(b);
    uint32_t r = ((uint32_t)__bfloat16_as_ushort(hb) << 16) | (uint32_t)__bfloat16_as_ushort(ha);
    return r;
}

// =================================================================
// Weight prep (convs): fp32 [Cout][64][3][3] -> bf16 hi/lo [tap][o][72]
// =================================================================
__global__ void prep_w_k(const float* __restrict__ w,
                         __nv_bfloat16* __restrict__ oh,
                         __nv_bfloat16* __restrict__ ol, int Cout)
{
    int i = blockIdx.x * 256 + threadIdx.x;
    int total = 9 * Cout * 64;
    if (i >= total) return;
    int ci  = i & 63;
    int o   = (i >> 6) % Cout;
    int tap = i / (64 * Cout);
    float v = w[(size_t)(o * 64 + ci) * 9 + tap];
    __nv_bfloat16 h = __float2bfloat16(v);
    __nv_bfloat16 l = __float2bfloat16(v - __bfloat162float(h));
    size_t d = (size_t)(tap * Cout + o) * 72 + ci;
    oh[d] = h;
    ol[d] = l;
}

// =================================================================
// Weight prep (dcn einsum): w_dcn [64 o][64 gc][9 k] -> per-chunk MMA B
// fragments. chunk covers gk pair (2*chunk, 2*chunk+1); k_local 0..7 =
// channels of gk0, 8..15 = channels of gk1. Lane (qr,qc): o = nt*8+qr,
// word0 = (k=2qc,2qc+1), word1 = (k=2qc+8,2qc+9).
// =================================================================
__global__ void prep_wd_frag(const float* __restrict__ wdcn,
                             uint2* __restrict__ fh, uint2* __restrict__ fl)
{
    int i = blockIdx.x * 256 + threadIdx.x;
    if (i >= 36 * 8 * 32) return;
    int lane = i & 31;
    int nt = (i >> 5) & 7;
    int chunk = i >> 8;
    int qr = lane >> 2, qc = lane & 3;
    int o = nt * 8 + qr;
    uint32_t wh[2], wl[2];
#pragma unroll
    for (int half = 0; half < 2; half++) {
        int gk = chunk * 2 + half;
        int g = gk / 9, kt = gk - 9 * g;
        int c = qc * 2;
        float wa = wdcn[(size_t)(o * 64 + g * 8 + c) * 9 + kt];
        float wb = wdcn[(size_t)(o * 64 + g * 8 + c + 1) * 9 + kt];
        float ha = __bfloat162float(__float2bfloat16(wa));
        float hb = __bfloat162float(__float2bfloat16(wb));
        wh[half] = pack_bf16x2(ha, hb);
        wl[half] = pack_bf16x2(wa - ha, wb - hb);
    }
    fh[i] = make_uint2(wh[0], wh[1]);
    fl[i] = make_uint2(wl[0], wl[1]);
}

// =================================================================
// 3x3 conv (pad 1, Cin=64) via warp mma.sync bf16 hi/lo split.
// (unchanged from R7 except PRE path unused for conv1 now)
// =================================================================
constexpr int PS = 72;
constexpr int PATCH_BYTES = 180 * PS * 2;

template<int NT, int NCHUNK, bool PRE, bool RESID>
__global__ __launch_bounds__(128) void conv_mma(
    const float* __restrict__ in, const float* __restrict__ in2,
    const float* __restrict__ pbias,
    const __nv_bfloat16* __restrict__ wh, const __nv_bfloat16* __restrict__ wl,
    const float* __restrict__ bias, const float* __restrict__ resid,
    float* __restrict__ out, int Cout)
{
    extern __shared__ __align__(16) char smem[];
    __nv_bfloat16* phi = (__nv_bfloat16*)smem;
    __nv_bfloat16* plo = (__nv_bfloat16*)(smem + PATCH_BYTES);
    __nv_bfloat16* bhiS = (__nv_bfloat16*)(smem + 2 * PATCH_BYTES);
    __nv_bfloat16* bloS = bhiS + NT * 8 * PS;

    const int tid  = threadIdx.x;
    const int wp   = tid >> 5;
    const int lane = tid & 31;
    const int qr   = lane >> 2;
    const int qc   = lane & 3;

    const int wx0 = blockIdx.x * 16;
    const int hy0 = blockIdx.y * 8;
    const int zz  = blockIdx.z;
    const int nc  = zz % NCHUNK;
    const int b   = zz / NCHUNK;
    const int co0 = nc * NT * 8;

    const float* inb  = in  + (size_t)b * CIN * HW;
    const float* in2b = PRE ? (in2 + (size_t)b * CIN * HW) : nullptr;
    for (int e = tid; e < 180 * 64; e += 128) {
        int x  = e % 18;
        int y  = (e / 18) % 10;
        int ci = e / 180;
        int gy = hy0 + y - 1;
        int gx = wx0 + x - 1;
        float v = 0.f;
        if ((unsigned)gy < HH && (unsigned)gx < WW) {
            int gi = ci * HW + gy * WW + gx;
            v = inb[gi];
            if (PRE) {
                v += in2b[gi] + pbias[ci];
                v = (v >= 0.f) ? v : 0.2f * v;
            }
        }
        __nv_bfloat16 h = __float2bfloat16(v);
        __nv_bfloat16 l = __float2bfloat16(v - __bfloat162float(h));
        int d = (y * 18 + x) * PS + ci;
        phi[d] = h;
        plo[d] = l;
    }

    float acc[2][NT][4];
#pragma unroll
    for (int mt = 0; mt < 2; mt++)
#pragma unroll
        for (int nt = 0; nt < NT; nt++)
#pragma unroll
            for (int j = 0; j < 4; j++) acc[mt][nt][j] = 0.f;

#pragma unroll 1
    for (int tap = 0; tap < 9; tap++) {
        const int ky = tap / 3, kx = tap % 3;
        __syncthreads();
        {
            const uint4* sH = (const uint4*)(wh + (size_t)(tap * Cout + co0) * PS);
            const uint4* sL = (const uint4*)(wl + (size_t)(tap * Cout + co0) * PS);
            uint4* dH = (uint4*)bhiS;
            uint4* dL = (uint4*)bloS;
            const int n4 = NT * 8 * PS / 8;
            for (int e = tid; e < n4; e += 128) { dH[e] = sH[e]; dL[e] = sL[e]; }
        }
        __syncthreads();

#pragma unroll
        for (int kc = 0; kc < 4; kc++) {
            const int ci0 = kc * 16;
            uint32_t ah[2][4], al[2][4];
#pragma unroll
            for (int mt = 0; mt < 2; mt++) {
                int yrow = 2 * wp + mt + ky;
                int base = (yrow * 18 + qr + kx) * PS + ci0 + qc * 2;
                const uint32_t* ph = (const uint32_t*)phi;
                const uint32_t* pl = (const uint32_t*)plo;
                int i0 = base >> 1;
                int i1 = (base + 8 * PS) >> 1;
                ah[mt][0] = ph[i0];
                ah[mt][1] = ph[i1];
                ah[mt][2] = ph[i0 + 4];
                ah[mt][3] = ph[i1 + 4];
                al[mt][0] = pl[i0];
                al[mt][1] = pl[i1];
                al[mt][2] = pl[i0 + 4];
                al[mt][3] = pl[i1 + 4];
            }
#pragma unroll
            for (int nt = 0; nt < NT; nt++) {
                int bb = ((nt * 8 + qr) * PS + ci0 + qc * 2) >> 1;
                uint32_t bh[2], bl[2];
                bh[0] = ((const uint32_t*)bhiS)[bb];
                bh[1] = ((const uint32_t*)bhiS)[bb + 4];
                bl[0] = ((const uint32_t*)bloS)[bb];
                bl[1] = ((const uint32_t*)bloS)[bb + 4];
#pragma unroll
                for (int mt = 0; mt < 2; mt++) {
                    mma16816(acc[mt][nt], ah[mt], bh);
                    mma16816(acc[mt][nt], ah[mt], bl);
                    mma16816(acc[mt][nt], al[mt], bh);
                }
            }
        }
    }

#pragma unroll
    for (int mt = 0; mt < 2; mt++) {
        int gy = hy0 + 2 * wp + mt;
        int gx = wx0 + qr;
#pragma unroll
        for (int nt = 0; nt < NT; nt++) {
            int o = co0 + nt * 8 + qc * 2;
            float b0 = bias[o], b1 = bias[o + 1];
            size_t i00 = ((size_t)(b * Cout + o) * HH + gy) * WW + gx;
            size_t i01 = i00 + HW;
            float v0 = acc[mt][nt][0] + b0;
            float v1 = acc[mt][nt][1] + b1;
            float v2 = acc[mt][nt][2] + b0;
            float v3 = acc[mt][nt][3] + b1;
            if (RESID) {
                v0 += resid[i00];     v1 += resid[i01];
                v2 += resid[i00 + 8]; v3 += resid[i01 + 8];
            }
            out[i00] = v0;
            out[i01] = v1;
            out[i00 + 8] = v2;
            out[i01 + 8] = v3;
        }
    }
}

// =================================================================
// Deformable sampling + grouped einsum via mma.sync, fused bias+leaky.
// Block: 128 threads, 128 pixels (8 rows x 16 cols). Thread t owns
// pixel (y=t>>4, x=t&15). K=576 split into 36 k16 chunks (2 gk each):
// per chunk each thread samples 16 values (2 gk x 8 c), writes bf16
// hi/lo to smem A-tile [y][x][18-pad], then warps run hi/lo-split MMAs
// with pre-packed B fragments straight from global.
// =================================================================
__global__ __launch_bounds__(128) void deform_mma_k(
    const float* __restrict__ x, const float* __restrict__ om,
    const uint2* __restrict__ fragH, const uint2* __restrict__ fragL,
    const float* __restrict__ bdcn, float* __restrict__ fea)
{
    __shared__ uint32_t sAh[128 * 9];
    __shared__ uint32_t sAl[128 * 9];

    const int tid  = threadIdx.x;
    const int wp   = tid >> 5;
    const int lane = tid & 31;
    const int qr   = lane >> 2;
    const int qc   = lane & 3;
    const int px   = tid & 15;
    const int py   = tid >> 4;

    const int wx0 = blockIdx.x * 16;
    const int hy0 = blockIdx.y * 8;
    const int b   = blockIdx.z;
    const int w0  = wx0 + px;
    const int h0  = hy0 + py;
    const int pidx = h0 * WW + w0;

    const float* omb = om + (size_t)b * 216 * HW;
    const float* xb  = x  + (size_t)b * 64  * HW;

    float acc[2][8][4];
#pragma unroll
    for (int mt = 0; mt < 2; mt++)
#pragma unroll
        for (int nt = 0; nt < 8; nt++)
#pragma unroll
            for (int j = 0; j < 4; j++) acc[mt][nt][j] = 0.f;

    int g = 0, kt = 0;   // tracks gk = 2*chunk + half

#pragma unroll 1
    for (int chunk = 0; chunk < 36; chunk++) {
#pragma unroll
        for (int half = 0; half < 2; half++) {
            const int gk = chunk * 2 + half;
            float oy = __ldg(&omb[(size_t)gk * HW + pidx]);
            float ox = __ldg(&omb[(size_t)(72 + gk) * HW + pidx]);
            float ml = __ldg(&omb[(size_t)(144 + gk) * HW + pidx]);
            float m  = 1.f / (1.f + __expf(-ml));

            float pyf = (float)(h0 + kt / 3 - 1) + oy;
            float pxf = (float)(w0 + kt % 3 - 1) + ox;
            float y0f = floorf(pyf), x0f = floorf(pxf);
            float fy = pyf - y0f, fx = pxf - x0f;
            int y0 = (int)y0f, x0 = (int)x0f;
            int y1 = y0 + 1,  x1 = x0 + 1;

            float vy0 = (y0 >= 0 && y0 < HH) ? 1.f : 0.f;
            float vy1 = (y1 >= 0 && y1 < HH) ? 1.f : 0.f;
            float vx0 = (x0 >= 0 && x0 < WW) ? 1.f : 0.f;
            float vx1 = (x1 >= 0 && x1 < WW) ? 1.f : 0.f;
            int yc0 = min(max(y0, 0), HH - 1);
            int yc1 = min(max(y1, 0), HH - 1);
            int xc0 = min(max(x0, 0), WW - 1);
            int xc1 = min(max(x1, 0), WW - 1);

            float w00 = (1.f - fy) * (1.f - fx) * vy0 * vx0 * m;
            float w01 = (1.f - fy) * fx        * vy0 * vx1 * m;
            float w10 = fy        * (1.f - fx) * vy1 * vx0 * m;
            float w11 = fy        * fx         * vy1 * vx1 * m;

            int i00 = yc0 * WW + xc0;
            int i01 = yc0 * WW + xc1;
            int i10 = yc1 * WW + xc0;
            int i11 = yc1 * WW + xc1;

            const float* xg = xb + g * 8 * HW;
#pragma unroll
            for (int c = 0; c < 8; c += 2) {
                const float* xc0p = xg + c * HW;
                const float* xc1p = xg + (c + 1) * HW;
                float v0 = w00 * __ldg(xc0p + i00) + w01 * __ldg(xc0p + i01)
                         + w10 * __ldg(xc0p + i10) + w11 * __ldg(xc0p + i11);
                float v1 = w00 * __ldg(xc1p + i00) + w01 * __ldg(xc1p + i01)
                         + w10 * __ldg(xc1p + i10) + w11 * __ldg(xc1p + i11);
                float h0v = __bfloat162float(__float2bfloat16(v0));
                float h1v = __bfloat162float(__float2bfloat16(v1));
                int widx = tid * 9 + half * 4 + (c >> 1);
                sAh[widx] = pack_bf16x2(h0v, h1v);
                sAl[widx] = pack_bf16x2(v0 - h0v, v1 - h1v);
            }
            if (++kt == 9) { kt = 0; g++; }
        }
        __syncthreads();

        // ---- MMA phase ----
        uint32_t ah[2][4], al[2][4];
#pragma unroll
        for (int mt = 0; mt < 2; mt++) {
            int y = 2 * wp + mt;
            int i0 = (y * 16 + qr) * 9 + qc;
            int i1 = (y * 16 + qr + 8) * 9 + qc;
            ah[mt][0] = sAh[i0];
            ah[mt][1] = sAh[i1];
            ah[mt][2] = sAh[i0 + 4];
            ah[mt][3] = sAh[i1 + 4];
            al[mt][0] = sAl[i0];
            al[mt][1] = sAl[i1];
            al[mt][2] = sAl[i0 + 4];
            al[mt][3] = sAl[i1 + 4];
        }
        const uint2* fh = fragH + (size_t)chunk * 256 + lane;
        const uint2* fl = fragL + (size_t)chunk * 256 + lane;
#pragma unroll
        for (int nt = 0; nt < 8; nt++) {
            uint2 bhv2 = __ldg(fh + nt * 32);
            uint2 blv2 = __ldg(fl + nt * 32);
            uint32_t bh[2] = {bhv2.x, bhv2.y};
            uint32_t bl[2] = {blv2.x, blv2.y};
#pragma unroll
            for (int mt = 0; mt < 2; mt++) {
                mma16816(acc[mt][nt], ah[mt], bh);
                mma16816(acc[mt][nt], ah[mt], bl);
                mma16816(acc[mt][nt], al[mt], bh);
            }
        }
        __syncthreads();
    }

    // ---- epilogue: bias + leaky, final fea ----
#pragma unroll
    for (int mt = 0; mt < 2; mt++) {
        int gy = hy0 + 2 * wp + mt;
        int gx = wx0 + qr;
        int pi = gy * WW + gx;
#pragma unroll
        for (int nt = 0; nt < 8; nt++) {
            int o = nt * 8 + qc * 2;
            float b0 = bdcn[o], b1 = bdcn[o + 1];
            float v0 = acc[mt][nt][0] + b0;
            float v1 = acc[mt][nt][1] + b1;
            float v2 = acc[mt][nt][2] + b0;
            float v3 = acc[mt][nt][3] + b1;
            v0 = (v0 >= 0.f) ? v0 : 0.2f * v0;
            v1 = (v1 >= 0.f) ? v1 : 0.2f * v1;
            v2 = (v2 >= 0.f) ? v2 : 0.2f * v2;
            v3 = (v3 >= 0.f) ? v3 : 0.2f * v3;
            size_t o0i = (size_t)(b * 64 + o) * HW + pi;
            size_t o1i = o0i + HW;
            fea[o0i]     = v0;
            fea[o1i]     = v1;
            fea[o0i + 8] = v2;
            fea[o1i + 8] = v3;
        }
    }
}

// =================================================================
// Launch
// =================================================================
extern "C" void kernel_launch(void* const* d_in, const int* in_sizes, int n_in,
                              void* d_out, int out_size)
{
    const float* x       = (const float*)d_in[0];
    const float* offset  = (const float*)d_in[1];
    const float* w_off   = (const float*)d_in[2];
    const float* b_off   = (const float*)d_in[3];
    const float* w_dcn   = (const float*)d_in[4];
    const float* b_dcn   = (const float*)d_in[5];
    const float* w_conv1 = (const float*)d_in[6];
    const float* b_conv1 = (const float*)d_in[7];
    float* out = (float*)d_out;

    void *p_om, *p_fea, *p_wAh, *p_wAl, *p_wBh, *p_wBl, *p_fH, *p_fL;
    cudaGetSymbolAddress(&p_om, g_om);
    cudaGetSymbolAddress(&p_fea, g_fea);
    cudaGetSymbolAddress(&p_wAh, g_wAh);
    cudaGetSymbolAddress(&p_wAl, g_wAl);
    cudaGetSymbolAddress(&p_wBh, g_wBh);
    cudaGetSymbolAddress(&p_wBl, g_wBl);
    cudaGetSymbolAddress(&p_fH, g_fragH);
    cudaGetSymbolAddress(&p_fL, g_fragL);
    float* om  = (float*)p_om;
    float* fea = (float*)p_fea;

    const int SMEM_A = 2 * PATCH_BYTES + 2 * 9 * 8 * PS * 2;   // 72576
    const int SMEM_B = 2 * PATCH_BYTES + 2 * 8 * 8 * PS * 2;   // 70272

    cudaFuncSetAttribute((const void*)conv_mma<9, 3, false, false>,
                         cudaFuncAttributeMaxDynamicSharedMemorySize, SMEM_A);
    cudaFuncSetAttribute((const void*)conv_mma<8, 1, false, true>,
                         cudaFuncAttributeMaxDynamicSharedMemorySize, SMEM_B);

    // 0) weight prep
    prep_w_k<<<(9 * 216 * 64 + 255) / 256, 256>>>(w_off,  (__nv_bfloat16*)p_wAh, (__nv_bfloat16*)p_wAl, 216);
    prep_w_k<<<(9 * 64 * 64 + 255) / 256, 256>>>(w_conv1, (__nv_bfloat16*)p_wBh, (__nv_bfloat16*)p_wBl, 64);
    prep_wd_frag<<<(36 * 8 * 32 + 255) / 256, 256>>>(w_dcn, (uint2*)p_fH, (uint2*)p_fL);

    // 1) offset conv: 64 -> 216 (mma.sync), 3 chunks of 72 channels
    conv_mma<9, 3, false, false><<<dim3(6, 12, BB * 3), 128, SMEM_A>>>(
        offset, nullptr, nullptr,
        (const __nv_bfloat16*)p_wAh, (const __nv_bfloat16*)p_wAl,
        b_off, nullptr, om, 216);

    // 2) deformable sampling + full grouped einsum (mma.sync) + bias + leaky
    deform_mma_k<<<dim3(6, 12, BB), 128>>>(
        x, om, (const uint2*)p_fH, (const uint2*)p_fL, b_dcn, fea);

    // 3) conv1: 64 -> 64 (mma.sync) + residual
    conv_mma<8, 1, false, true><<<dim3(6, 12, BB), 128, SMEM_B>>>(
        fea, nullptr, nullptr,
        (const __nv_bfloat16*)p_wBh, (const __nv_bfloat16*)p_wBl,
        b_conv1, x, out, 64);
}

// round 9
// speedup vs baseline: 2.5794x; 1.0922x over previous
#include <cuda_runtime.h>
#include <cuda_bf16.h>
#include <cstdint>
#include <math.h>

// Problem constants
#define HH 96
#define WW 96
#define BB 4
#define CIN 64
#define HW (HH*WW)

// ---------------- scratch (no allocations allowed) ----------------
__device__ float g_om[(size_t)BB * 216 * HW];        // offset-conv output
__device__ float g_fea[(size_t)BB * 64 * HW];        // activated dcn output
__device__ uint2 g_fAH[36 * 27 * 32];                // offset-conv B frags hi [chunk][ntG][lane]
__device__ uint2 g_fAL[36 * 27 * 32];                // lo
__device__ uint2 g_fBH[36 * 8 * 32];                 // conv1 B frags hi
__device__ uint2 g_fBL[36 * 8 * 32];                 // lo
__device__ uint2 g_fDH[36 * 8 * 32];                 // w_dcn B frags hi
__device__ uint2 g_fDL[36 * 8 * 32];                 // lo

// ---------------- warp MMA: m16n8k16 row.col f32.bf16.bf16.f32 ----------------
__device__ __forceinline__ void mma16816(float* d, const uint32_t* a, const uint32_t* b) {
    asm volatile(
        "mma.sync.aligned.m16n8k16.row.col.f32.bf16.bf16.f32 "
        "{%0,%1,%2,%3}, {%4,%5,%6,%7}, {%8,%9}, {%0,%1,%2,%3};"
        : "+f"(d[0]), "+f"(d[1]), "+f"(d[2]), "+f"(d[3])
        : "r"(a[0]), "r"(a[1]), "r"(a[2]), "r"(a[3]), "r"(b[0]), "r"(b[1]));
}

__device__ __forceinline__ uint32_t pack_bf16x2(float a, float b) {
    __nv_bfloat16 ha = __float2bfloat16(a);
    __nv_bfloat16 hb = __float2bfloat16(b);
    return ((uint32_t)__bfloat16_as_ushort(hb) << 16) | (uint32_t)__bfloat16_as_ushort(ha);
}

// =================================================================
// Conv weight prep: fp32 w[Cout][64ci][9tap] -> MMA B fragments, hi/lo.
// chunk = tap*4 + kc (k16 over ci0=kc*16). Lane(qr,qc), row o=ntG*8+qr:
// word0 = (ci0+2qc, +1), word1 = (ci0+8+2qc, +1).
// =================================================================
__global__ void prep_conv_frag(const float* __restrict__ w,
                               uint2* __restrict__ fh, uint2* __restrict__ fl,
                               int Cout)
{
    int NTOT = Cout >> 3;
    int total = 36 * NTOT * 32;
    int i = blockIdx.x * 256 + threadIdx.x;
    if (i >= total) return;
    int lane = i & 31;
    int ntG  = (i >> 5) % NTOT;
    int chunk = i / (NTOT * 32);
    int tap = chunk >> 2;
    int ci0 = (chunk & 3) * 16;
    int qr = lane >> 2, qc = lane & 3;
    int o = ntG * 8 + qr;
    uint32_t wh[2], wl[2];
#pragma unroll
    for (int half = 0; half < 2; half++) {
        int ci = ci0 + half * 8 + qc * 2;
        float wa = w[(size_t)(o * 64 + ci) * 9 + tap];
        float wb = w[(size_t)(o * 64 + ci + 1) * 9 + tap];
        float ha = __bfloat162float(__float2bfloat16(wa));
        float hb = __bfloat162float(__float2bfloat16(wb));
        wh[half] = pack_bf16x2(ha, hb);
        wl[half] = pack_bf16x2(wa - ha, wb - hb);
    }
    fh[i] = make_uint2(wh[0], wh[1]);
    fl[i] = make_uint2(wl[0], wl[1]);
}

// =================================================================
// DCN einsum weight prep: w_dcn[64o][64gc][9k] -> per-chunk B frags.
// chunk covers gk pair (2c, 2c+1): k 0..7 = channels of gk0, 8..15 gk1.
// =================================================================
__global__ void prep_wd_frag(const float* __restrict__ wdcn,
                             uint2* __restrict__ fh, uint2* __restrict__ fl)
{
    int i = blockIdx.x * 256 + threadIdx.x;
    if (i >= 36 * 8 * 32) return;
    int lane = i & 31;
    int nt = (i >> 5) & 7;
    int chunk = i >> 8;
    int qr = lane >> 2, qc = lane & 3;
    int o = nt * 8 + qr;
    uint32_t wh[2], wl[2];
#pragma unroll
    for (int half = 0; half < 2; half++) {
        int gk = chunk * 2 + half;
        int g = gk / 9, kt = gk - 9 * g;
        int c = qc * 2;
        float wa = wdcn[(size_t)(o * 64 + g * 8 + c) * 9 + kt];
        float wb = wdcn[(size_t)(o * 64 + g * 8 + c + 1) * 9 + kt];
        float ha = __bfloat162float(__float2bfloat16(wa));
        float hb = __bfloat162float(__float2bfloat16(wb));
        wh[half] = pack_bf16x2(ha, hb);
        wl[half] = pack_bf16x2(wa - ha, wb - hb);
    }
    fh[i] = make_uint2(wh[0], wh[1]);
    fl[i] = make_uint2(wl[0], wl[1]);
}

// =================================================================
// 3x3 conv (pad 1, Cin=64) via mma.sync, B fragments from global.
// Block: 128 threads (4 warps), M=128 px (8x16), warp wp -> rows 2wp,2wp+1.
// Patch [10*18 px][72 ci] bf16 hi/lo staged ONCE; single __syncthreads.
// Main loop (36 chunks): 16 LDS(A) + 2*NT LDG.64(B) + 3*2*NT HMMA.
// =================================================================
constexpr int PS = 72;
constexpr int PATCH_BYTES = 180 * PS * 2;   // 25920

template<int NT, int NCHUNK, bool RESID>
__global__ __launch_bounds__(128) void conv_mma(
    const float* __restrict__ in,
    const uint2* __restrict__ fragH, const uint2* __restrict__ fragL,
    const float* __restrict__ bias, const float* __restrict__ resid,
    float* __restrict__ out, int Cout)
{
    extern __shared__ __align__(16) char smem[];
    __nv_bfloat16* phi = (__nv_bfloat16*)smem;
    __nv_bfloat16* plo = (__nv_bfloat16*)(smem + PATCH_BYTES);

    const int tid  = threadIdx.x;
    const int wp   = tid >> 5;
    const int lane = tid & 31;
    const int qr   = lane >> 2;
    const int qc   = lane & 3;

    const int wx0 = blockIdx.x * 16;
    const int hy0 = blockIdx.y * 8;
    const int zz  = blockIdx.z;
    const int nc  = zz % NCHUNK;
    const int b   = zz / NCHUNK;
    const int NTOT = Cout >> 3;
    const int co0 = nc * NT * 8;

    const float* inb = in + (size_t)b * CIN * HW;
    for (int e = tid; e < 180 * 64; e += 128) {
        int x  = e % 18;
        int y  = (e / 18) % 10;
        int ci = e / 180;
        int gy = hy0 + y - 1;
        int gx = wx0 + x - 1;
        float v = 0.f;
        if ((unsigned)gy < HH && (unsigned)gx < WW)
            v = inb[ci * HW + gy * WW + gx];
        __nv_bfloat16 h = __float2bfloat16(v);
        __nv_bfloat16 l = __float2bfloat16(v - __bfloat162float(h));
        int d = (y * 18 + x) * PS + ci;
        phi[d] = h;
        plo[d] = l;
    }
    __syncthreads();

    float acc[2][NT][4];
#pragma unroll
    for (int mt = 0; mt < 2; mt++)
#pragma unroll
        for (int nt = 0; nt < NT; nt++)
#pragma unroll
            for (int j = 0; j < 4; j++) acc[mt][nt][j] = 0.f;

#pragma unroll 1
    for (int tap = 0; tap < 9; tap++) {
        const int ky = tap / 3, kx = tap % 3;
#pragma unroll
        for (int kc = 0; kc < 4; kc++) {
            const int ci0 = kc * 16;
            uint32_t ah[2][4], al[2][4];
#pragma unroll
            for (int mt = 0; mt < 2; mt++) {
                int yrow = 2 * wp + mt + ky;
                int base = (yrow * 18 + qr + kx) * PS + ci0 + qc * 2;
                const uint32_t* ph = (const uint32_t*)phi;
                const uint32_t* pl = (const uint32_t*)plo;
                int i0 = base >> 1;
                int i1 = (base + 8 * PS) >> 1;
                ah[mt][0] = ph[i0];
                ah[mt][1] = ph[i1];
                ah[mt][2] = ph[i0 + 4];
                ah[mt][3] = ph[i1 + 4];
                al[mt][0] = pl[i0];
                al[mt][1] = pl[i1];
                al[mt][2] = pl[i0 + 4];
                al[mt][3] = pl[i1 + 4];
            }
            const int chunk = tap * 4 + kc;
            const uint2* fh = fragH + ((size_t)chunk * NTOT + (co0 >> 3)) * 32 + lane;
            const uint2* fl = fragL + ((size_t)chunk * NTOT + (co0 >> 3)) * 32 + lane;
#pragma unroll
            for (int nt = 0; nt < NT; nt++) {
                uint2 bh2 = __ldg(fh + nt * 32);
                uint2 bl2 = __ldg(fl + nt * 32);
                uint32_t bh[2] = {bh2.x, bh2.y};
                uint32_t bl[2] = {bl2.x, bl2.y};
#pragma unroll
                for (int mt = 0; mt < 2; mt++) {
                    mma16816(acc[mt][nt], ah[mt], bh);
                    mma16816(acc[mt][nt], ah[mt], bl);
                    mma16816(acc[mt][nt], al[mt], bh);
                }
            }
        }
    }

#pragma unroll
    for (int mt = 0; mt < 2; mt++) {
        int gy = hy0 + 2 * wp + mt;
        int gx = wx0 + qr;
#pragma unroll
        for (int nt = 0; nt < NT; nt++) {
            int o = co0 + nt * 8 + qc * 2;
            float b0 = bias[o], b1 = bias[o + 1];
            size_t i00 = ((size_t)(b * Cout + o) * HH + gy) * WW + gx;
            size_t i01 = i00 + HW;
            float v0 = acc[mt][nt][0] + b0;
            float v1 = acc[mt][nt][1] + b1;
            float v2 = acc[mt][nt][2] + b0;
            float v3 = acc[mt][nt][3] + b1;
            if (RESID) {
                v0 += resid[i00];     v1 += resid[i01];
                v2 += resid[i00 + 8]; v3 += resid[i01 + 8];
            }
            out[i00] = v0;
            out[i01] = v1;
            out[i00 + 8] = v2;
            out[i01 + 8] = v3;
        }
    }
}

// =================================================================
// Deformable sampling + grouped einsum via mma.sync, fused bias+leaky.
// Warp-private A staging: warp wp's MMA A-frags come only from its own
// 32 pixels (tids 32wp..32wp+31) -> __syncwarp instead of __syncthreads.
// =================================================================
__global__ __launch_bounds__(128) void deform_mma_k(
    const float* __restrict__ x, const float* __restrict__ om,
    const uint2* __restrict__ fragH, const uint2* __restrict__ fragL,
    const float* __restrict__ bdcn, float* __restrict__ fea)
{
    __shared__ uint32_t sAh[128 * 9];
    __shared__ uint32_t sAl[128 * 9];

    const int tid  = threadIdx.x;
    const int wp   = tid >> 5;
    const int lane = tid & 31;
    const int qr   = lane >> 2;
    const int qc   = lane & 3;
    const int px   = tid & 15;
    const int py   = tid >> 4;

    const int wx0 = blockIdx.x * 16;
    const int hy0 = blockIdx.y * 8;
    const int b   = blockIdx.z;
    const int w0  = wx0 + px;
    const int h0  = hy0 + py;
    const int pidx = h0 * WW + w0;

    const float* omb = om + (size_t)b * 216 * HW;
    const float* xb  = x  + (size_t)b * 64  * HW;

    float acc[2][8][4];
#pragma unroll
    for (int mt = 0; mt < 2; mt++)
#pragma unroll
        for (int nt = 0; nt < 8; nt++)
#pragma unroll
            for (int j = 0; j < 4; j++) acc[mt][nt][j] = 0.f;

    int g = 0, kt = 0;   // tracks gk = 2*chunk + half

#pragma unroll 1
    for (int chunk = 0; chunk < 36; chunk++) {
#pragma unroll
        for (int half = 0; half < 2; half++) {
            const int gk = chunk * 2 + half;
            float oy = __ldg(&omb[(size_t)gk * HW + pidx]);
            float ox = __ldg(&omb[(size_t)(72 + gk) * HW + pidx]);
            float ml = __ldg(&omb[(size_t)(144 + gk) * HW + pidx]);
            float m  = 1.f / (1.f + __expf(-ml));

            float pyf = (float)(h0 + kt / 3 - 1) + oy;
            float pxf = (float)(w0 + kt % 3 - 1) + ox;
            float y0f = floorf(pyf), x0f = floorf(pxf);
            float fy = pyf - y0f, fx = pxf - x0f;
            int y0 = (int)y0f, x0 = (int)x0f;
            int y1 = y0 + 1,  x1 = x0 + 1;

            float vy0 = (y0 >= 0 && y0 < HH) ? 1.f : 0.f;
            float vy1 = (y1 >= 0 && y1 < HH) ? 1.f : 0.f;
            float vx0 = (x0 >= 0 && x0 < WW) ? 1.f : 0.f;
            float vx1 = (x1 >= 0 && x1 < WW) ? 1.f : 0.f;
            int yc0 = min(max(y0, 0), HH - 1);
            int yc1 = min(max(y1, 0), HH - 1);
            int xc0 = min(max(x0, 0), WW - 1);
            int xc1 = min(max(x1, 0), WW - 1);

            float w00 = (1.f - fy) * (1.f - fx) * vy0 * vx0 * m;
            float w01 = (1.f - fy) * fx        * vy0 * vx1 * m;
            float w10 = fy        * (1.f - fx) * vy1 * vx0 * m;
            float w11 = fy        * fx         * vy1 * vx1 * m;

            int i00 = yc0 * WW + xc0;
            int i01 = yc0 * WW + xc1;
            int i10 = yc1 * WW + xc0;
            int i11 = yc1 * WW + xc1;

            const float* xg = xb + g * 8 * HW;
#pragma unroll
            for (int c = 0; c < 8; c += 2) {
                const float* xc0p = xg + c * HW;
                const float* xc1p = xg + (c + 1) * HW;
                float v0 = w00 * __ldg(xc0p + i00) + w01 * __ldg(xc0p + i01)
                         + w10 * __ldg(xc0p + i10) + w11 * __ldg(xc0p + i11);
                float v1 = w00 * __ldg(xc1p + i00) + w01 * __ldg(xc1p + i01)
                         + w10 * __ldg(xc1p + i10) + w11 * __ldg(xc1p + i11);
                float h0v = __bfloat162float(__float2bfloat16(v0));
                float h1v = __bfloat162float(__float2bfloat16(v1));
                int widx = tid * 9 + half * 4 + (c >> 1);
                sAh[widx] = pack_bf16x2(h0v, h1v);
                sAl[widx] = pack_bf16x2(v0 - h0v, v1 - h1v);
            }
            if (++kt == 9) { kt = 0; g++; }
        }
        __syncwarp();

        // ---- MMA phase (reads only this warp's 32-pixel span) ----
        uint32_t ah[2][4], al[2][4];
#pragma unroll
        for (int mt = 0; mt < 2; mt++) {
            int y = 2 * wp + mt;
            int i0 = (y * 16 + qr) * 9 + qc;
            int i1 = (y * 16 + qr + 8) * 9 + qc;
            ah[mt][0] = sAh[i0];
            ah[mt][1] = sAh[i1];
            ah[mt][2] = sAh[i0 + 4];
            ah[mt][3] = sAh[i1 + 4];
            al[mt][0] = sAl[i0];
            al[mt][1] = sAl[i1];
            al[mt][2] = sAl[i0 + 4];
            al[mt][3] = sAl[i1 + 4];
        }
        const uint2* fh = fragH + (size_t)chunk * 256 + lane;
        const uint2* fl = fragL + (size_t)chunk * 256 + lane;
#pragma unroll
        for (int nt = 0; nt < 8; nt++) {
            uint2 bhv2 = __ldg(fh + nt * 32);
            uint2 blv2 = __ldg(fl + nt * 32);
            uint32_t bh[2] = {bhv2.x, bhv2.y};
            uint32_t bl[2] = {blv2.x, blv2.y};
#pragma unroll
            for (int mt = 0; mt < 2; mt++) {
                mma16816(acc[mt][nt], ah[mt], bh);
                mma16816(acc[mt][nt], ah[mt], bl);
                mma16816(acc[mt][nt], al[mt], bh);
            }
        }
        __syncwarp();
    }

    // ---- epilogue: bias + leaky, final fea ----
#pragma unroll
    for (int mt = 0; mt < 2; mt++) {
        int gy = hy0 + 2 * wp + mt;
        int gx = wx0 + qr;
        int pi = gy * WW + gx;
#pragma unroll
        for (int nt = 0; nt < 8; nt++) {
            int o = nt * 8 + qc * 2;
            float b0 = bdcn[o], b1 = bdcn[o + 1];
            float v0 = acc[mt][nt][0] + b0;
            float v1 = acc[mt][nt][1] + b1;
            float v2 = acc[mt][nt][2] + b0;
            float v3 = acc[mt][nt][3] + b1;
            v0 = (v0 >= 0.f) ? v0 : 0.2f * v0;
            v1 = (v1 >= 0.f) ? v1 : 0.2f * v1;
            v2 = (v2 >= 0.f) ? v2 : 0.2f * v2;
            v3 = (v3 >= 0.f) ? v3 : 0.2f * v3;
            size_t o0i = (size_t)(b * 64 + o) * HW + pi;
            size_t o1i = o0i + HW;
            fea[o0i]     = v0;
            fea[o1i]     = v1;
            fea[o0i + 8] = v2;
            fea[o1i + 8] = v3;
        }
    }
}

// =================================================================
// Launch
// =================================================================
extern "C" void kernel_launch(void* const* d_in, const int* in_sizes, int n_in,
                              void* d_out, int out_size)
{
    const float* x       = (const float*)d_in[0];
    const float* offset  = (const float*)d_in[1];
    const float* w_off   = (const float*)d_in[2];
    const float* b_off   = (const float*)d_in[3];
    const float* w_dcn   = (const float*)d_in[4];
    const float* b_dcn   = (const float*)d_in[5];
    const float* w_conv1 = (const float*)d_in[6];
    const float* b_conv1 = (const float*)d_in[7];
    float* out = (float*)d_out;

    void *p_om, *p_fea, *p_AH, *p_AL, *p_BH, *p_BL, *p_DH, *p_DL;
    cudaGetSymbolAddress(&p_om, g_om);
    cudaGetSymbolAddress(&p_fea, g_fea);
    cudaGetSymbolAddress(&p_AH, g_fAH);
    cudaGetSymbolAddress(&p_AL, g_fAL);
    cudaGetSymbolAddress(&p_BH, g_fBH);
    cudaGetSymbolAddress(&p_BL, g_fBL);
    cudaGetSymbolAddress(&p_DH, g_fDH);
    cudaGetSymbolAddress(&p_DL, g_fDL);
    float* om  = (float*)p_om;
    float* fea = (float*)p_fea;

    const int SMEM_C = 2 * PATCH_BYTES;   // 51840

    cudaFuncSetAttribute((const void*)conv_mma<9, 3, false>,
                         cudaFuncAttributeMaxDynamicSharedMemorySize, SMEM_C);
    cudaFuncSetAttribute((const void*)conv_mma<8, 1, true>,
                         cudaFuncAttributeMaxDynamicSharedMemorySize, SMEM_C);

    // 0) weight prep (fragment packing)
    prep_conv_frag<<<(36 * 27 * 32 + 255) / 256, 256>>>(w_off, (uint2*)p_AH, (uint2*)p_AL, 216);
    prep_conv_frag<<<(36 * 8 * 32 + 255) / 256, 256>>>(w_conv1, (uint2*)p_BH, (uint2*)p_BL, 64);
    prep_wd_frag<<<(36 * 8 * 32 + 255) / 256, 256>>>(w_dcn, (uint2*)p_DH, (uint2*)p_DL);

    // 1) offset conv: 64 -> 216 (mma.sync), 3 chunks of 72 channels
    conv_mma<9, 3, false><<<dim3(6, 12, BB * 3), 128, SMEM_C>>>(
        offset, (const uint2*)p_AH, (const uint2*)p_AL, b_off, nullptr, om, 216);

    // 2) deformable sampling + grouped einsum + bias + leaky
    deform_mma_k<<<dim3(6, 12, BB), 128>>>(
        x, om, (const uint2*)p_DH, (const uint2*)p_DL, b_dcn, fea);

    // 3) conv1: 64 -> 64 (mma.sync) + residual
    conv_mma<8, 1, true><<<dim3(6, 12, BB), 128, SMEM_C>>>(
        fea, (const uint2*)p_BH, (const uint2*)p_BL, b_conv1, x, out, 64);
}